// round 1
// baseline (speedup 1.0000x reference)
#include <cuda_runtime.h>

// out[65536,64] = xa[65536,256] @ wa[256,64] + xb[65536,256] @ wb[256,64]
// Single fused GEMM: K = 512 (first 256 from xa/wa, last 256 from xb/wb).
//
// fp32 SIMT path, packed fma.rn.f32x2 (FFMA2) for full 128 MAC/cyc/SM rate.
// CTA: 256 rows x 64 cols. 256 threads, each 8 rows x 8 cols (4 f32x2 pairs).

#define M_TILE 256
#define KC 32
#define XPAD 4          // sx row stride = 36 words -> conflict-free scalar reads
#define N_OUT 64
#define K_HALF 256

__device__ __forceinline__ void ffma2(unsigned long long& d,
                                      unsigned long long a,
                                      unsigned long long b) {
    asm("fma.rn.f32x2 %0, %1, %2, %0;" : "+l"(d) : "l"(a), "l"(b));
}

__device__ __forceinline__ unsigned long long pack2(float x) {
    unsigned long long r;
    asm("mov.b64 %0, {%1, %1};" : "=l"(r) : "f"(x));
    return r;
}

__device__ __forceinline__ float2 unpack2(unsigned long long v) {
    float2 f;
    asm("mov.b64 {%0, %1}, %2;" : "=f"(f.x), "=f"(f.y) : "l"(v));
    return f;
}

__global__ __launch_bounds__(256, 2)
void sshe_agg_kernel(const float* __restrict__ xa,
                     const float* __restrict__ xb,
                     const float* __restrict__ wa,
                     const float* __restrict__ wb,
                     float* __restrict__ out) {
    __shared__ float sx[M_TILE][KC + XPAD];   // 36864 B
    __shared__ float sw[KC][N_OUT];           //  8192 B

    const int tid = threadIdx.x;
    const int tc = tid & 7;        // col group: cols [tc*8, tc*8+8)
    const int tr = tid >> 3;       // row lane: rows tr + i*32, i=0..7
    const long long row0 = (long long)blockIdx.x * M_TILE;

    // 8 rows x 4 f32x2 col-pairs
    unsigned long long acc[8][4];
#pragma unroll
    for (int i = 0; i < 8; i++)
#pragma unroll
        for (int j = 0; j < 4; j++) acc[i][j] = 0ull;  // {0.f, 0.f}

    // loader mapping
    const int xlr = tid >> 3;        // base row group (0..31)
    const int xlk = (tid & 7) * 4;   // k offset within chunk (0,4,...,28)
    const int wlk = tid >> 3;        // w chunk row (0..31)
    const int wln = (tid & 7) * 8;   // w col offset (0,8,...,56)

    for (int kc = 0; kc < 2 * K_HALF; kc += KC) {
        const float* __restrict__ xsrc = (kc < K_HALF) ? xa : xb;
        const float* __restrict__ wsrc = (kc < K_HALF) ? wa : wb;
        const int kb = kc & (K_HALF - 1);

        __syncthreads();  // previous chunk fully consumed

        // stage x: 256 rows x 32 k  (8 float4 per thread, coalesced)
#pragma unroll
        for (int j = 0; j < 8; j++) {
            const int r = xlr + j * 32;
            const float4 v = *(const float4*)&xsrc[(row0 + r) * K_HALF + kb + xlk];
            *(float4*)&sx[r][xlk] = v;
        }
        // stage w: 32 k x 64 cols (2 float4 per thread)
        {
            const float4 v0 = *(const float4*)&wsrc[(long long)(kb + wlk) * N_OUT + wln];
            const float4 v1 = *(const float4*)&wsrc[(long long)(kb + wlk) * N_OUT + wln + 4];
            *(float4*)&sw[wlk][wln] = v0;
            *(float4*)&sw[wlk][wln + 4] = v1;
        }
        __syncthreads();

#pragma unroll
        for (int k = 0; k < KC; k++) {
            // 8 contiguous w cols for this thread: two 128-bit LDS,
            // register pairs feed FFMA2 directly (no repack).
            float4 w0 = *(const float4*)&sw[k][tc * 8];
            float4 w1 = *(const float4*)&sw[k][tc * 8 + 4];
            unsigned long long wp[4];
            wp[0] = *(unsigned long long*)&w0.x;
            wp[1] = *(unsigned long long*)&w0.z;
            wp[2] = *(unsigned long long*)&w1.x;
            wp[3] = *(unsigned long long*)&w1.z;
#pragma unroll
            for (int i = 0; i < 8; i++) {
                const unsigned long long xp = pack2(sx[tr + i * 32][k]);
                ffma2(acc[i][0], xp, wp[0]);
                ffma2(acc[i][1], xp, wp[1]);
                ffma2(acc[i][2], xp, wp[2]);
                ffma2(acc[i][3], xp, wp[3]);
            }
        }
    }

    // epilogue: two 128-bit stores per row, coalesced across the warp
#pragma unroll
    for (int i = 0; i < 8; i++) {
        const long long r = row0 + tr + i * 32;
        float* o = &out[r * N_OUT + tc * 8];
        float2 a0 = unpack2(acc[i][0]);
        float2 a1 = unpack2(acc[i][1]);
        float2 a2 = unpack2(acc[i][2]);
        float2 a3 = unpack2(acc[i][3]);
        float4 v0 = make_float4(a0.x, a0.y, a1.x, a1.y);
        float4 v1 = make_float4(a2.x, a2.y, a3.x, a3.y);
        *(float4*)&o[0] = v0;
        *(float4*)&o[4] = v1;
    }
}

extern "C" void kernel_launch(void* const* d_in, const int* in_sizes, int n_in,
                              void* d_out, int out_size) {
    const float* xa = (const float*)d_in[0];
    const float* xb = (const float*)d_in[1];
    const float* wa = (const float*)d_in[2];
    const float* wb = (const float*)d_in[3];
    float* out = (float*)d_out;

    const int batch = in_sizes[0] / K_HALF;   // 65536
    dim3 grid(batch / M_TILE);                // 256 CTAs
    dim3 block(256);
    sshe_agg_kernel<<<grid, block>>>(xa, xb, wa, wb, out);
}

// round 4
// speedup vs baseline: 3.4508x; 3.4508x over previous
#include <cuda_runtime.h>
#include <cuda_bf16.h>
#include <cstdint>

// out[65536,64] = xa[65536,256]@wa[256,64] + xb[65536,256]@wb[256,64]
// bf16 hi/lo split (3 terms: HH + HL + LH), mma.sync.m16n8k16, fp32 accum.
// A fragments built directly from global fp32 (no smem, no ldmatrix).
// B pre-packed in fragment order by a pre-kernel; smem is a verbatim copy.
// CTA: 8 warps x 16 rows = 128 rows, N=64 (8 n-tiles/warp), K=512 (8 chunks).

#define NCHUNK 8
#define KC     64
#define M_TILE 128
#define NOUT   64

// fragment-packed B, index = (((c*4+ks)*8+ni)*32+L)*4+q
//   q0 = bhi{k0,k0+1}  q1 = bhi{k0+8,k0+9}  q2 = blo{k0,k0+1}  q3 = blo{k0+8,k0+9}
//   k0 = c*64 + ks*16 + (L&3)*2,  n = ni*8 + (L>>2)
__device__ __align__(16) uint32_t g_wfrag[NCHUNK * 4 * 8 * 32 * 4];  // 128 KB

// pack two fp32 -> bf16x2, first arg in LOW 16 bits
__device__ __forceinline__ uint32_t bf2(float lo, float hi) {
    uint32_t r;
    asm("cvt.rn.bf16x2.f32 %0, %1, %2;" : "=r"(r) : "f"(hi), "f"(lo));
    return r;
}

__device__ __forceinline__ void split2(float x0, float x1,
                                       uint32_t& hp, uint32_t& lp) {
    hp = bf2(x0, x1);
    float h0 = __uint_as_float(hp << 16);
    float h1 = __uint_as_float(hp & 0xffff0000u);
    lp = bf2(x0 - h0, x1 - h1);
}

__device__ __forceinline__ void mma16816(float* c, const uint32_t* a,
                                         uint32_t b0, uint32_t b1) {
    asm volatile(
        "mma.sync.aligned.m16n8k16.row.col.f32.bf16.bf16.f32 "
        "{%0,%1,%2,%3}, {%4,%5,%6,%7}, {%8,%9}, {%0,%1,%2,%3};"
        : "+f"(c[0]), "+f"(c[1]), "+f"(c[2]), "+f"(c[3])
        : "r"(a[0]), "r"(a[1]), "r"(a[2]), "r"(a[3]), "r"(b0), "r"(b1));
}

// ---- pre-kernel: build fragment-packed hi/lo B images ----
__global__ void wconv_kernel(const float* __restrict__ wa,
                             const float* __restrict__ wb) {
    int id = blockIdx.x * 256 + threadIdx.x;   // 0..32767
    int q  = id & 3;
    int L  = (id >> 2) & 31;
    int ni = (id >> 7) & 7;
    int ks = (id >> 10) & 3;
    int c  = id >> 12;
    int k0 = c * 64 + ks * 16 + (L & 3) * 2 + (q & 1) * 8;
    int n  = ni * 8 + (L >> 2);
    float v0 = (k0 < 256) ? wa[k0 * 64 + n] : wb[(k0 - 256) * 64 + n];
    float v1 = (k0 + 1 < 256) ? wa[(k0 + 1) * 64 + n] : wb[(k0 - 255) * 64 + n];
    uint32_t hp, lp;
    split2(v0, v1, hp, lp);
    g_wfrag[id] = (q >> 1) ? lp : hp;
}

// ---- main kernel ----
__global__ void __launch_bounds__(256, 1)
sshe_mma_kernel(const float* __restrict__ xa, const float* __restrict__ xb,
                float* __restrict__ out) {
    extern __shared__ uint32_t sB[];   // 32768 words = 128 KB, verbatim g_wfrag
    const int tid = threadIdx.x;
    const int L = tid & 31;
    const int wid = tid >> 5;

    // copy B fragments to smem (identity layout)
    {
        const uint4* src = (const uint4*)g_wfrag;
        uint4* dst = (uint4*)sB;
#pragma unroll
        for (int i = 0; i < 32; i++) dst[tid + i * 256] = src[tid + i * 256];
    }
    __syncthreads();

    // A fragment coordinates for this thread
    const int row = blockIdx.x * M_TILE + wid * 16 + (L >> 2);  // a0/a2 row
    const int kk2 = (L & 3) * 2;                                 // k within 8

    float acc[8][4];
#pragma unroll
    for (int i = 0; i < 8; i++)
#pragma unroll
        for (int j = 0; j < 4; j++) acc[i][j] = 0.f;

    float2 cur[16], nxt[16];

    // load x fragments for chunk c:
    //   slot ks*4+0: (row,   k0)   -> a0
    //   slot ks*4+1: (row+8, k0)   -> a1
    //   slot ks*4+2: (row,   k0+8) -> a2
    //   slot ks*4+3: (row+8, k0+8) -> a3
    auto load_chunk = [&](int c, float2* dst) {
        const float* __restrict__ xsrc = (c < 4) ? xa : xb;
        const int kb = (c & 3) * KC + kk2;
        const float* p0 = xsrc + (size_t)row * 256 + kb;
        const float* p1 = xsrc + (size_t)(row + 8) * 256 + kb;
#pragma unroll
        for (int ks = 0; ks < 4; ks++) {
            dst[ks * 4 + 0] = *(const float2*)(p0 + ks * 16);
            dst[ks * 4 + 1] = *(const float2*)(p1 + ks * 16);
            dst[ks * 4 + 2] = *(const float2*)(p0 + ks * 16 + 8);
            dst[ks * 4 + 3] = *(const float2*)(p1 + ks * 16 + 8);
        }
    };

    load_chunk(0, cur);

#pragma unroll 2
    for (int c = 0; c < NCHUNK; c++) {
        if (c + 1 < NCHUNK) load_chunk(c + 1, nxt);
#pragma unroll
        for (int ks = 0; ks < 4; ks++) {
            uint32_t ah[4], al[4];
            split2(cur[ks * 4 + 0].x, cur[ks * 4 + 0].y, ah[0], al[0]);
            split2(cur[ks * 4 + 1].x, cur[ks * 4 + 1].y, ah[1], al[1]);
            split2(cur[ks * 4 + 2].x, cur[ks * 4 + 2].y, ah[2], al[2]);
            split2(cur[ks * 4 + 3].x, cur[ks * 4 + 3].y, ah[3], al[3]);
            const uint4* Bp = (const uint4*)sB;
            const int base = ((c * 4 + ks) * 8) * 32 + L;
#pragma unroll
            for (int ni = 0; ni < 8; ni++) {
                uint4 B = Bp[base + ni * 32];
                mma16816(acc[ni], ah, B.x, B.y);   // hi*hi
                mma16816(acc[ni], ah, B.z, B.w);   // hi*lo
                mma16816(acc[ni], al, B.x, B.y);   // lo*hi
            }
        }
        if (c + 1 < NCHUNK) {
#pragma unroll
            for (int i = 0; i < 16; i++) cur[i] = nxt[i];
        }
    }

    // epilogue: c0,c1 -> (row, 2kk+{0,1}); c2,c3 -> (row+8, ...)
#pragma unroll
    for (int ni = 0; ni < 8; ni++) {
        float* o0 = out + (size_t)row * 64 + ni * 8 + kk2;
        float* o1 = out + (size_t)(row + 8) * 64 + ni * 8 + kk2;
        *(float2*)o0 = make_float2(acc[ni][0], acc[ni][1]);
        *(float2*)o1 = make_float2(acc[ni][2], acc[ni][3]);
    }
}

extern "C" void kernel_launch(void* const* d_in, const int* in_sizes, int n_in,
                              void* d_out, int out_size) {
    const float* xa = (const float*)d_in[0];
    const float* xb = (const float*)d_in[1];
    const float* wa = (const float*)d_in[2];
    const float* wb = (const float*)d_in[3];
    float* out = (float*)d_out;

    cudaFuncSetAttribute(sshe_mma_kernel,
                         cudaFuncAttributeMaxDynamicSharedMemorySize,
                         131072);

    wconv_kernel<<<128, 256>>>(wa, wb);

    const int batch = in_sizes[0] / 256;     // 65536
    sshe_mma_kernel<<<batch / M_TILE, 256, 131072>>>(xa, xb, out);
}

// round 5
// speedup vs baseline: 4.3794x; 1.2691x over previous
#include <cuda_runtime.h>
#include <cuda_fp16.h>
#include <cstdint>

// out[65536,64] = xa[65536,256]@wa[256,64] + xb[65536,256]@wb[256,64]
// fp16 two-term scheme: A split (xh + xl, both fp16, exact to ~2^-22),
// B single fp16 (wh). out = x @ fp16(w); error ~2e-4 << 1e-3.
// mma.sync.m16n8k16.f32.f16.f16.f32. A frags straight from global fp32.
// B pre-packed in exact fragment order (64 KB) -> smem verbatim copy
// -> 2 CTAs/SM (16 warps). CTA: 128 rows x 64 cols, K=512 in 16 chunks of 32.

#define NCHUNK 16
#define M_TILE 128

// fragment-packed B: index (((c*2+ks)*8+ni)*32+L) -> uint2 {b0,b1}
//   b0 = wh{k0,k0+1}, b1 = wh{k0+8,k0+9}; k0 = c*32+ks*16+(L&3)*2, n = ni*8+(L>>2)
__device__ __align__(16) uint2 g_wfrag[NCHUNK * 2 * 8 * 32];   // 8192 -> 64 KB

__device__ __forceinline__ uint32_t h2pack(float lo, float hi) {
    uint32_t r;
    asm("cvt.rn.f16x2.f32 %0, %1, %2;" : "=r"(r) : "f"(hi), "f"(lo));
    return r;
}

__device__ __forceinline__ void h2unpack(uint32_t p, float& lo, float& hi) {
    asm("{ .reg .b16 l, h; mov.b32 {l, h}, %2;\n\t"
        "cvt.f32.f16 %0, l; cvt.f32.f16 %1, h; }"
        : "=f"(lo), "=f"(hi) : "r"(p));
}

__device__ __forceinline__ void split2h(float x0, float x1,
                                        uint32_t& hp, uint32_t& lp) {
    hp = h2pack(x0, x1);
    float h0, h1;
    h2unpack(hp, h0, h1);
    lp = h2pack(x0 - h0, x1 - h1);
}

__device__ __forceinline__ void mma16816(float* c, const uint32_t* a,
                                         uint32_t b0, uint32_t b1) {
    asm volatile(
        "mma.sync.aligned.m16n8k16.row.col.f32.f16.f16.f32 "
        "{%0,%1,%2,%3}, {%4,%5,%6,%7}, {%8,%9}, {%0,%1,%2,%3};"
        : "+f"(c[0]), "+f"(c[1]), "+f"(c[2]), "+f"(c[3])
        : "r"(a[0]), "r"(a[1]), "r"(a[2]), "r"(a[3]), "r"(b0), "r"(b1));
}

// ---- pre-kernel: pack fp16(w) into fragment order ----
__global__ void wconv_kernel(const float* __restrict__ wa,
                             const float* __restrict__ wb) {
    int id = blockIdx.x * 256 + threadIdx.x;   // 0..8191
    int L  = id & 31;
    int ni = (id >> 5) & 7;
    int ks = (id >> 8) & 1;
    int c  = id >> 9;                          // 0..15
    int k0 = c * 32 + ks * 16 + (L & 3) * 2;   // global k
    int n  = ni * 8 + (L >> 2);
    const float* __restrict__ w = (c < 8) ? wa : wb;
    int kk = k0 & 255;
    float v0 = w[kk * 64 + n];
    float v1 = w[(kk + 1) * 64 + n];
    float v8 = w[(kk + 8) * 64 + n];
    float v9 = w[(kk + 9) * 64 + n];
    g_wfrag[id] = make_uint2(h2pack(v0, v1), h2pack(v8, v9));
}

// ---- main kernel ----
__global__ void __launch_bounds__(256, 2)
sshe_mma_kernel(const float* __restrict__ xa, const float* __restrict__ xb,
                float* __restrict__ out) {
    extern __shared__ uint2 sB[];   // 8192 entries, verbatim g_wfrag
    const int tid = threadIdx.x;
    const int L = tid & 31;
    const int wid = tid >> 5;

    // copy B fragments to smem (identity layout)
    {
        const uint4* src = (const uint4*)g_wfrag;
        uint4* dst = (uint4*)sB;
#pragma unroll
        for (int i = 0; i < 16; i++) dst[tid + i * 256] = src[tid + i * 256];
    }
    __syncthreads();

    const int row = blockIdx.x * M_TILE + wid * 16 + (L >> 2);
    const int kk2 = (L & 3) * 2;

    float acc[8][4];
#pragma unroll
    for (int i = 0; i < 8; i++)
#pragma unroll
        for (int j = 0; j < 4; j++) acc[i][j] = 0.f;

    float2 cur[8], nxt[8];

    // chunk c (32 k): slots per ks: (row,k0),(row+8,k0),(row,k0+8),(row+8,k0+8)
    auto load_chunk = [&](int c, float2* dst) {
        const float* __restrict__ xsrc = (c < 8) ? xa : xb;
        const int kb = (c & 7) * 32 + kk2;
        const float* p0 = xsrc + (size_t)row * 256 + kb;
        const float* p1 = xsrc + (size_t)(row + 8) * 256 + kb;
#pragma unroll
        for (int ks = 0; ks < 2; ks++) {
            dst[ks * 4 + 0] = *(const float2*)(p0 + ks * 16);
            dst[ks * 4 + 1] = *(const float2*)(p1 + ks * 16);
            dst[ks * 4 + 2] = *(const float2*)(p0 + ks * 16 + 8);
            dst[ks * 4 + 3] = *(const float2*)(p1 + ks * 16 + 8);
        }
    };

    load_chunk(0, cur);

#pragma unroll 2
    for (int c = 0; c < NCHUNK; c++) {
        if (c + 1 < NCHUNK) load_chunk(c + 1, nxt);
#pragma unroll
        for (int ks = 0; ks < 2; ks++) {
            uint32_t ah[4], al[4];
            split2h(cur[ks * 4 + 0].x, cur[ks * 4 + 0].y, ah[0], al[0]);
            split2h(cur[ks * 4 + 1].x, cur[ks * 4 + 1].y, ah[1], al[1]);
            split2h(cur[ks * 4 + 2].x, cur[ks * 4 + 2].y, ah[2], al[2]);
            split2h(cur[ks * 4 + 3].x, cur[ks * 4 + 3].y, ah[3], al[3]);
            const int base = ((c * 2 + ks) * 8) * 32 + L;
#pragma unroll
            for (int ni = 0; ni < 8; ni++) {
                uint2 B = sB[base + ni * 32];
                mma16816(acc[ni], ah, B.x, B.y);   // xh * wh
                mma16816(acc[ni], al, B.x, B.y);   // xl * wh
            }
        }
        if (c + 1 < NCHUNK) {
#pragma unroll
            for (int i = 0; i < 8; i++) cur[i] = nxt[i];
        }
    }

    // epilogue: c0,c1 -> (row, ni*8+kk2+{0,1}); c2,c3 -> (row+8, ...)
#pragma unroll
    for (int ni = 0; ni < 8; ni++) {
        float* o0 = out + (size_t)row * 64 + ni * 8 + kk2;
        float* o1 = out + (size_t)(row + 8) * 64 + ni * 8 + kk2;
        *(float2*)o0 = make_float2(acc[ni][0], acc[ni][1]);
        *(float2*)o1 = make_float2(acc[ni][2], acc[ni][3]);
    }
}

extern "C" void kernel_launch(void* const* d_in, const int* in_sizes, int n_in,
                              void* d_out, int out_size) {
    const float* xa = (const float*)d_in[0];
    const float* xb = (const float*)d_in[1];
    const float* wa = (const float*)d_in[2];
    const float* wb = (const float*)d_in[3];
    float* out = (float*)d_out;

    cudaFuncSetAttribute(sshe_mma_kernel,
                         cudaFuncAttributeMaxDynamicSharedMemorySize, 65536);

    wconv_kernel<<<32, 256>>>(wa, wb);

    const int batch = in_sizes[0] / 256;     // 65536
    sshe_mma_kernel<<<batch / M_TILE, 256, 65536>>>(xa, xb, out);
}